// round 16
// baseline (speedup 1.0000x reference)
#include <cuda_runtime.h>
#include <cuda_bf16.h>
#include <cstdint>

#define BB 8
#define CC 64
#define NN 100000
#define R3 32768   // 32^3
#define BPP 4      // batches per pass (2 passes): scratch = 32MB, L2-resident

// Scratch for ONE PASS (4 batches): sums in [bl, v, c] layout so one point's
// channel-adds are contiguous. 32MB + 512KB -> stays L2-resident even against
// the pass's ~102MB feature stream (the full-size 64MB version partially
// evicted, charging DRAM round-trips to both atomics and transpose reads).
__device__ float g_sums[(size_t)BPP * R3 * CC];
__device__ int   g_cnt[BPP * R3];

// ---------------------------------------------------------------------------
// Zero the scratch right BEFORE the atomics so the zeroed lines are L2-hot.
__global__ void __launch_bounds__(256) zero_kernel() {
    const int SUMS4 = (BPP * R3 * CC) / 4;  // 2,097,152
    const int CNT4  = (BPP * R3) / 4;       // 32,768
    const int TOTAL = SUMS4 + CNT4;
    float4 z4 = make_float4(0.f, 0.f, 0.f, 0.f);
    int stride = gridDim.x * blockDim.x;
    for (int i = blockIdx.x * blockDim.x + threadIdx.x; i < TOTAL; i += stride) {
        if (i < SUMS4) reinterpret_cast<float4*>(g_sums)[i] = z4;
        else           reinterpret_cast<int4*>(g_cnt)[i - SUMS4] = make_int4(0,0,0,0);
    }
}

// ---------------------------------------------------------------------------
// Point kernel with COALESCED REDs (R13 structure, + pass offset b0).
// Block = 256 threads handles 64 points x 64 channels of one batch.
//   Phase A (t<64): coords -> voxel index, coords output, count atomic.
//   Phase B: coalesced channel-major feature loads (LDG.128), register 4x4
//            micro-transpose, store point-major into XOR-swizzled float4 smem.
//   Phase C: warp-RED where 16 consecutive lanes cover one point's 256B of
//            channels -> 16 full sectors / 4 lines per warp-RED.
// mode: 0 = no coords output, 1 = int64 coords, 2 = float coords
__global__ void __launch_bounds__(256) point_kernel(
        const float* __restrict__ feat,
        const float* __restrict__ coords,
        char* out_coords, int mode, int b0) {
    __shared__ float4 s4[64 * 16];   // s4[p*16 + (q ^ (p>>2))]
    __shared__ int voxel_s[64];

    int t  = threadIdx.x;
    int bl = blockIdx.y;             // scratch batch slot 0..BPP-1
    int b  = b0 + bl;                // real batch
    int n0 = blockIdx.x * 64;
    int npts = NN - n0; if (npts > 64) npts = 64;   // 64 or 32

    // ---- Phase A: voxel index + coords out + counts (threads 0..npts-1) ----
    if (t < npts) {
        const float* cb = coords + (size_t)b * 3 * NN + n0 + t;
        float x = __ldcs(cb);
        float y = __ldcs(cb + NN);
        float z = __ldcs(cb + 2 * NN);
        // clip(coord*R, 0, R-1) then round-to-nearest-even (matches jnp.round)
        int vx = (int)rintf(fminf(fmaxf(x * 32.f, 0.f), 31.f));
        int vy = (int)rintf(fminf(fmaxf(y * 32.f, 0.f), 31.f));
        int vz = (int)rintf(fminf(fmaxf(z * 32.f, 0.f), 31.f));
        int vox = vx * 1024 + vy * 32 + vz;
        voxel_s[t] = vox;
        atomicAdd(&g_cnt[bl * R3 + vox], 1);
        if (mode == 1) {
            long long* oc = reinterpret_cast<long long*>(out_coords) + (size_t)b * 3 * NN + n0 + t;
            oc[0]      = (long long)vx;
            oc[NN]     = (long long)vy;
            oc[2 * NN] = (long long)vz;
        } else if (mode == 2) {
            float* oc = reinterpret_cast<float*>(out_coords) + (size_t)b * 3 * NN + n0 + t;
            oc[0]      = (float)vx;
            oc[NN]     = (float)vy;
            oc[2 * NN] = (float)vz;
        }
    }

    // ---- Phase B: coalesced loads + transpose into swizzled smem ----
    int a  = t >> 4;   // channel quad 0..15
    int bq = t & 15;   // point quad 0..15
    if (bq * 4 < npts) {
        const float* fb = feat + ((size_t)b * CC + a * 4) * NN + n0 + bq * 4;
        float4 r0 = __ldcs((const float4*)(fb));
        float4 r1 = __ldcs((const float4*)(fb + NN));
        float4 r2 = __ldcs((const float4*)(fb + 2 * (size_t)NN));
        float4 r3 = __ldcs((const float4*)(fb + 3 * (size_t)NN));
        int sw = a ^ bq;
        s4[(bq * 4 + 0) * 16 + sw] = make_float4(r0.x, r1.x, r2.x, r3.x);
        s4[(bq * 4 + 1) * 16 + sw] = make_float4(r0.y, r1.y, r2.y, r3.y);
        s4[(bq * 4 + 2) * 16 + sw] = make_float4(r0.z, r1.z, r2.z, r3.z);
        s4[(bq * 4 + 3) * 16 + sw] = make_float4(r0.w, r1.w, r2.w, r3.w);
    }
    __syncthreads();

    // ---- Phase C: coalesced vector REDs (16 lanes = one point's 256B) ----
#pragma unroll
    for (int k = 0; k < 4; k++) {
        int idx = k * 256 + t;
        int p = idx >> 4;
        int q = idx & 15;
        if (p < npts) {
            float4 v = s4[p * 16 + (q ^ (p >> 2))];
            float* dst = g_sums + ((size_t)(bl * R3 + voxel_s[p])) * CC + q * 4;
            asm volatile("red.global.add.v4.f32 [%0], {%1,%2,%3,%4};"
                         :: "l"(dst), "f"(v.x), "f"(v.y), "f"(v.z), "f"(v.w)
                         : "memory");
        }
    }
}

// ---------------------------------------------------------------------------
// Transpose [bl, v, c] -> [b, c, v] fused with the mean (x 1/max(cnt,1)).
// R13 64-voxel x 64-channel tiles (16.9KB smem -> 8 blocks/SM, full occ;
// the 128-voxel variant regressed via occupancy). Read-only on the scratch.
__global__ void __launch_bounds__(256) transpose_mean_kernel(float* __restrict__ out, int b0) {
    __shared__ float tile[64 * 65];  // padded: conflict-free transposed reads
    __shared__ float rcp[64];

    int bl  = blockIdx.y;
    int b   = b0 + bl;
    int v0  = blockIdx.x * 64;
    int tid = threadIdx.x;  // 256 threads

    const float4* src4 = reinterpret_cast<const float4*>(
        &g_sums[((size_t)bl * R3 + v0) * CC]);
#pragma unroll
    for (int e4 = tid; e4 < 1024; e4 += 256) {
        float4 vv = src4[e4];
        int lin = e4 * 4;
        int v = lin >> 6;
        int c = lin & 63;
        tile[v * 65 + c + 0] = vv.x;
        tile[v * 65 + c + 1] = vv.y;
        tile[v * 65 + c + 2] = vv.z;
        tile[v * 65 + c + 3] = vv.w;
    }
    if (tid < 64) {
        int cnt = g_cnt[bl * R3 + v0 + tid];
        rcp[tid] = 1.0f / fmaxf((float)cnt, 1.0f);
    }
    __syncthreads();

    float* obase = out + (size_t)b * CC * R3 + v0;
#pragma unroll
    for (int q = tid; q < 1024; q += 256) {
        int lin = q * 4;
        int c  = lin >> 6;
        int vi = lin & 63;
        float4 o;
        o.x = tile[(vi + 0) * 65 + c] * rcp[vi + 0];
        o.y = tile[(vi + 1) * 65 + c] * rcp[vi + 1];
        o.z = tile[(vi + 2) * 65 + c] * rcp[vi + 2];
        o.w = tile[(vi + 3) * 65 + c] * rcp[vi + 3];
        __stcs(reinterpret_cast<float4*>(obase + (size_t)c * R3 + vi), o);
    }
}

// ---------------------------------------------------------------------------
extern "C" void kernel_launch(void* const* d_in, const int* in_sizes, int n_in,
                              void* d_out, int out_size) {
    const float* feat   = (const float*)d_in[0];  // [B, C, N] f32
    const float* coords = (const float*)d_in[1];  // [B, 3, N] f32

    const int FEAT_ELEMS  = BB * CC * R3;   // 16,777,216
    const int COORD_ELEMS = BB * 3 * NN;    // 2,400,000

    int mode;
    if (out_size >= FEAT_ELEMS + 2 * COORD_ELEMS) {
        mode = 1;  // int64 bytes after the f32 feat block
    } else if (out_size >= FEAT_ELEMS + COORD_ELEMS) {
        mode = 2;  // coords cast to f32
    } else {
        mode = 0;  // feat only
    }
    char* out_coords = (char*)d_out + (size_t)FEAT_ELEMS * sizeof(float);

    // Two passes of BPP=4 batches, reusing the 32MB scratch slice so it stays
    // L2-resident through each pass's zero -> atomics -> transpose chain.
    for (int pass = 0; pass < BB / BPP; pass++) {
        int b0 = pass * BPP;
        zero_kernel<<<2048, 256>>>();
        {
            dim3 grid((NN + 63) / 64, BPP);   // 1563 x 4
            point_kernel<<<grid, 256>>>(feat, coords, out_coords, mode, b0);
        }
        {
            dim3 grid(R3 / 64, BPP);          // 512 x 4
            transpose_mean_kernel<<<grid, 256>>>((float*)d_out, b0);
        }
    }
}

// round 17
// speedup vs baseline: 1.0459x; 1.0459x over previous
#include <cuda_runtime.h>
#include <cuda_bf16.h>
#include <cstdint>

#define BB 8
#define CC 64
#define NN 100000
#define R3 32768  // 32^3

// Scratch: sums in [b, v, c] layout so one point's channel-adds are contiguous.
// 64MB, effectively L2-resident during accumulation (R16 two-pass test showed
// DRAM=0% on the scratch even at 64MB; splitting it bought nothing).
__device__ float g_sums[(size_t)BB * R3 * CC];
__device__ int   g_cnt[BB * R3];

// ---------------------------------------------------------------------------
// Point kernel with COALESCED REDs (R13 structure, unchanged).
// Block = 256 threads handles 64 points x 64 channels of one batch.
//   Phase A (t<64): coords -> voxel index, coords output, count atomic.
//   Phase B: coalesced channel-major feature loads (LDG.128), register 4x4
//            micro-transpose, store point-major into XOR-swizzled float4 smem.
//   Phase C: warp-RED where 16 consecutive lanes cover one point's 256B of
//            channels -> 16 full sectors / 4 lines per warp-RED.
// mode: 0 = no coords output, 1 = int64 coords, 2 = float coords
__global__ void __launch_bounds__(256) point_kernel(
        const float* __restrict__ feat,
        const float* __restrict__ coords,
        char* out_coords, int mode) {
    __shared__ float4 s4[64 * 16];   // s4[p*16 + (q ^ (p>>2))]
    __shared__ int voxel_s[64];

    int t  = threadIdx.x;
    int b  = blockIdx.y;
    int n0 = blockIdx.x * 64;
    int npts = NN - n0; if (npts > 64) npts = 64;   // 64 or 32 (NN = 1562*64 + 32)

    // ---- Phase A: voxel index + coords out + counts (threads 0..npts-1) ----
    if (t < npts) {
        const float* cb = coords + (size_t)b * 3 * NN + n0 + t;
        float x = __ldcs(cb);
        float y = __ldcs(cb + NN);
        float z = __ldcs(cb + 2 * NN);
        // clip(coord*R, 0, R-1) then round-to-nearest-even (matches jnp.round)
        int vx = (int)rintf(fminf(fmaxf(x * 32.f, 0.f), 31.f));
        int vy = (int)rintf(fminf(fmaxf(y * 32.f, 0.f), 31.f));
        int vz = (int)rintf(fminf(fmaxf(z * 32.f, 0.f), 31.f));
        int vox = vx * 1024 + vy * 32 + vz;
        voxel_s[t] = vox;
        atomicAdd(&g_cnt[b * R3 + vox], 1);
        if (mode == 1) {
            long long* oc = reinterpret_cast<long long*>(out_coords) + (size_t)b * 3 * NN + n0 + t;
            oc[0]      = (long long)vx;
            oc[NN]     = (long long)vy;
            oc[2 * NN] = (long long)vz;
        } else if (mode == 2) {
            float* oc = reinterpret_cast<float*>(out_coords) + (size_t)b * 3 * NN + n0 + t;
            oc[0]      = (float)vx;
            oc[NN]     = (float)vy;
            oc[2 * NN] = (float)vz;
        }
    }

    // ---- Phase B: coalesced loads + transpose into swizzled smem ----
    int a  = t >> 4;   // channel quad 0..15 (channels 4a..4a+3)
    int bq = t & 15;   // point quad 0..15   (points 4bq..4bq+3)
    if (bq * 4 < npts) {
        const float* fb = feat + ((size_t)b * CC + a * 4) * NN + n0 + bq * 4;
        float4 r0 = __ldcs((const float4*)(fb));
        float4 r1 = __ldcs((const float4*)(fb + NN));
        float4 r2 = __ldcs((const float4*)(fb + 2 * (size_t)NN));
        float4 r3 = __ldcs((const float4*)(fb + 3 * (size_t)NN));
        int sw = a ^ bq;   // (p>>2) == bq for all 4 points of this quad
        s4[(bq * 4 + 0) * 16 + sw] = make_float4(r0.x, r1.x, r2.x, r3.x);
        s4[(bq * 4 + 1) * 16 + sw] = make_float4(r0.y, r1.y, r2.y, r3.y);
        s4[(bq * 4 + 2) * 16 + sw] = make_float4(r0.z, r1.z, r2.z, r3.z);
        s4[(bq * 4 + 3) * 16 + sw] = make_float4(r0.w, r1.w, r2.w, r3.w);
    }
    __syncthreads();

    // ---- Phase C: coalesced vector REDs (16 lanes = one point's 256B) ----
#pragma unroll
    for (int k = 0; k < 4; k++) {
        int idx = k * 256 + t;
        int p = idx >> 4;      // point 0..63 (16 consecutive lanes share p)
        int q = idx & 15;      // channel quad
        if (p < npts) {
            float4 v = s4[p * 16 + (q ^ (p >> 2))];
            float* dst = g_sums + ((size_t)(b * R3 + voxel_s[p])) * CC + q * 4;
            asm volatile("red.global.add.v4.f32 [%0], {%1,%2,%3,%4};"
                         :: "l"(dst), "f"(v.x), "f"(v.y), "f"(v.z), "f"(v.w)
                         : "memory");
        }
    }
}

// ---------------------------------------------------------------------------
// Transpose [b, v, c] -> [b, c, v] fused with the mean (x 1/max(cnt,1)).
// R13 64-voxel x 64-channel tiles (16.9KB smem -> 8 blocks/SM, full occ).
// READ-ONLY on the scratch.
__global__ void __launch_bounds__(256) transpose_mean_kernel(float* __restrict__ out) {
    __shared__ float tile[64 * 65];  // padded: conflict-free transposed reads
    __shared__ float rcp[64];

    int b   = blockIdx.y;
    int v0  = blockIdx.x * 64;
    int tid = threadIdx.x;  // 256 threads

    const float4* src4 = reinterpret_cast<const float4*>(
        &g_sums[((size_t)b * R3 + v0) * CC]);
#pragma unroll
    for (int e4 = tid; e4 < 1024; e4 += 256) {
        float4 vv = src4[e4];
        int lin = e4 * 4;
        int v = lin >> 6;
        int c = lin & 63;
        tile[v * 65 + c + 0] = vv.x;
        tile[v * 65 + c + 1] = vv.y;
        tile[v * 65 + c + 2] = vv.z;
        tile[v * 65 + c + 3] = vv.w;
    }
    if (tid < 64) {
        int cnt = g_cnt[b * R3 + v0 + tid];
        rcp[tid] = 1.0f / fmaxf((float)cnt, 1.0f);
    }
    __syncthreads();

    float* obase = out + (size_t)b * CC * R3 + v0;
#pragma unroll
    for (int q = tid; q < 1024; q += 256) {
        int lin = q * 4;
        int c  = lin >> 6;
        int vi = lin & 63;
        float4 o;
        o.x = tile[(vi + 0) * 65 + c] * rcp[vi + 0];
        o.y = tile[(vi + 1) * 65 + c] * rcp[vi + 1];
        o.z = tile[(vi + 2) * 65 + c] * rcp[vi + 2];
        o.w = tile[(vi + 3) * 65 + c] * rcp[vi + 3];
        __stcs(reinterpret_cast<float4*>(obase + (size_t)c * R3 + vi), o);
    }
}

// ---------------------------------------------------------------------------
extern "C" void kernel_launch(void* const* d_in, const int* in_sizes, int n_in,
                              void* d_out, int out_size) {
    const float* feat   = (const float*)d_in[0];  // [B, C, N] f32
    const float* coords = (const float*)d_in[1];  // [B, 3, N] f32

    const int FEAT_ELEMS  = BB * CC * R3;   // 16,777,216
    const int COORD_ELEMS = BB * 3 * NN;    // 2,400,000

    int mode;
    if (out_size >= FEAT_ELEMS + 2 * COORD_ELEMS) {
        mode = 1;  // int64 bytes after the f32 feat block
    } else if (out_size >= FEAT_ELEMS + COORD_ELEMS) {
        mode = 2;  // coords cast to f32
    } else {
        mode = 0;  // feat only
    }
    char* out_coords = (char*)d_out + (size_t)FEAT_ELEMS * sizeof(float);

    // 1) zero scratch via driver memset (graph-capturable memset nodes;
    //    no allocation). Runs immediately before the atomics so the zeroed
    //    lines are L2-hot when the REDs consume them.
    {
        void* sums_ptr = nullptr;
        void* cnt_ptr  = nullptr;
        cudaGetSymbolAddress(&sums_ptr, g_sums);
        cudaGetSymbolAddress(&cnt_ptr,  g_cnt);
        cudaMemsetAsync(sums_ptr, 0, (size_t)BB * R3 * CC * sizeof(float));
        cudaMemsetAsync(cnt_ptr,  0, (size_t)BB * R3 * sizeof(int));
    }
    // 2) scatter-accumulate per point (coalesced vector REDs)
    {
        dim3 grid((NN + 63) / 64, BB);   // 1563 x 8
        point_kernel<<<grid, 256>>>(feat, coords, out_coords, mode);
    }
    // 3) transpose + mean into d_out
    {
        dim3 grid(R3 / 64, BB);
        transpose_mean_kernel<<<grid, 256>>>((float*)d_out);
    }
}